// round 13
// baseline (speedup 1.0000x reference)
#include <cuda_runtime.h>
#include <cuda_fp16.h>
#include <cstdint>

#define B_    512
#define T1_   128
#define IN1_  64
#define H1_   256
#define IN3_  32
#define H3_   128
#define T3_   64
#define FCIN_ 3872
#define FEATC 3840

typedef unsigned long long u64;
typedef unsigned int u32;

// ---------------- device scratch ----------------
__device__ __align__(16) __half g_W1h[320 * 1024];   // [k][n], n=gate*256+j, pitch 2048B
__device__ __align__(16) __half g_W2h[320 * 1024];
__device__ __align__(16) float4 g_b1v4[H1_];         // (bi,bf,bg,bo) per j
__device__ __align__(16) float4 g_b2v4[H1_];
__device__ __align__(16) float  g_b3[H3_ * 4];       // [j][(bi,bf,bg,bo)]
__device__ float g_feat[B_ * FEATC];

// ---------------- scalar helpers ----------------
__device__ __forceinline__ float tapx(float x) {           // HW tanh (MUFU)
    float y; asm("tanh.approx.f32 %0, %1;" : "=f"(y) : "f"(x)); return y;
}
__device__ __forceinline__ float sga(float x) {            // sigmoid via tanh
    return fmaf(tapx(0.5f * x), 0.5f, 0.5f);
}
__device__ __forceinline__ u32 smem_u32(const void* p) {
    u32 a;
    asm("{ .reg .u64 t; cvta.to.shared.u64 t, %1; cvt.u32.u64 %0, t; }" : "=r"(a) : "l"(p));
    return a;
}

// ---------------- mma.sync / ldmatrix / cp.async ----------------
__device__ __forceinline__ void ldsm_x4(u32& r0, u32& r1, u32& r2, u32& r3, u32 addr) {
    asm volatile("ldmatrix.sync.aligned.m8n8.x4.shared.b16 {%0,%1,%2,%3}, [%4];"
                 : "=r"(r0), "=r"(r1), "=r"(r2), "=r"(r3) : "r"(addr));
}
// x4 trans: {r0,r1} = B-frag of n-tile at n_off, {r2,r3} = n-tile at n_off+8.
__device__ __forceinline__ void ldsm_x4t(u32& r0, u32& r1, u32& r2, u32& r3, u32 addr) {
    asm volatile("ldmatrix.sync.aligned.m8n8.x4.trans.shared.b16 {%0,%1,%2,%3}, [%4];"
                 : "=r"(r0), "=r"(r1), "=r"(r2), "=r"(r3) : "r"(addr));
}
__device__ __forceinline__ void mma16816(float* c, u32 a0, u32 a1, u32 a2, u32 a3,
                                         u32 b0, u32 b1) {
    asm volatile("mma.sync.aligned.m16n8k16.row.col.f32.f16.f16.f32 "
                 "{%0,%1,%2,%3}, {%4,%5,%6,%7}, {%8,%9}, {%0,%1,%2,%3};"
                 : "+f"(c[0]), "+f"(c[1]), "+f"(c[2]), "+f"(c[3])
                 : "r"(a0), "r"(a1), "r"(a2), "r"(a3), "r"(b0), "r"(b1));
}
__device__ __forceinline__ void cp16(u32 saddr, const void* gptr) {
    asm volatile("cp.async.cg.shared.global [%0], [%1], 16;" :: "r"(saddr), "l"(gptr));
}
__device__ __forceinline__ void cp_commit() {
    asm volatile("cp.async.commit_group;" ::: "memory");
}
template<int N> __device__ __forceinline__ void cp_wait() {
    asm volatile("cp.async.wait_group %0;" :: "n"(N) : "memory");
}

// ---------------- roleB (lstm3) smem layout: double-buffered A ----------------
#define ASTRIDE 336
#define BSTRIDE 1040
#define ABUFB   10752            // 32 rows x 336 (16-row blocks use half, same spacing)
#define SMB_A    0               // A0 at 0, A1 at 10752
#define SMB_BIAS 21504           // 2048 (float4[128])
#define SMB_B    23552           // + 160*1040 = 189952

// ---------------- roleA (lstm12, 16 rows) smem layout: 2xA + 3xB ----------------
#define APITCH12  656            // 16 rows x 656B = 10496
#define ABUFA     10496
#define BPITCH12  2064
#define TILE12    66048          // 32*2064
#define SA_A      0              // A0 at 0, A1 at 10496
#define SA_BIAS   20992          // float4[256] = 4096
#define SA_B0     25088
#define SA_B1     (SA_B0 + TILE12)
#define SA_B2     (SA_B1 + TILE12)
#define SMEM_MERGED (SA_B2 + TILE12)   // 223232 <= 227KB cap

// ---------------- weight prep ----------------
__global__ void prep_kernel(
    const float* __restrict__ Wih1, const float* __restrict__ Whh1,
    const float* __restrict__ bih1, const float* __restrict__ bhh1,
    const float* __restrict__ Wih2, const float* __restrict__ Whh2,
    const float* __restrict__ bih2, const float* __restrict__ bhh2,
    const float* __restrict__ bih3, const float* __restrict__ bhh3)
{
    int idx = blockIdx.x * blockDim.x + threadIdx.x;
    if (idx < 320 * 1024) {
        int k = idx >> 10, n = idx & 1023;
        int tau = n >> 8, j = n & 255;
        int g = tau * H1_ + j;
        float v1 = (k < IN1_) ? Wih1[g * IN1_ + k] : Whh1[g * H1_ + (k - IN1_)];
        float v2 = (k < IN1_) ? Wih2[g * IN1_ + k] : Whh2[g * H1_ + (k - IN1_)];
        g_W1h[idx] = __float2half_rn(v1);
        g_W2h[idx] = __float2half_rn(v2);
    }
    if (idx < H1_) {
        int j = idx;
        g_b1v4[j] = make_float4(bih1[j] + bhh1[j],
                                bih1[H1_ + j] + bhh1[H1_ + j],
                                bih1[2 * H1_ + j] + bhh1[2 * H1_ + j],
                                bih1[3 * H1_ + j] + bhh1[3 * H1_ + j]);
        g_b2v4[j] = make_float4(bih2[j] + bhh2[j],
                                bih2[H1_ + j] + bhh2[H1_ + j],
                                bih2[2 * H1_ + j] + bhh2[2 * H1_ + j],
                                bih2[3 * H1_ + j] + bhh2[3 * H1_ + j]);
    }
    if (idx < H3_ * 4) {
        int tau = idx & 3, j = idx >> 2;
        g_b3[j * 4 + tau] = bih3[tau * H3_ + j] + bhh3[tau * H3_ + j];
    }
}

// ---------------------------------------------------------------------------
// Merged LSTM kernel: 552 blocks x 256 threads (8 warps).
//   blocks 0..95    : roleA  = LSTM1/2, 16 rows/block; B streamed via cp.async
//                     (3 buffers, ONE sync per tile); A double-buffered (t&1)
//   blocks 96..407  : roleB32 = LSTM3, 32 rows/block (rows 0..9983)
//   blocks 408..551 : roleB16 = LSTM3, 16 rows/block (rows 9984..12287)
//                     half-size tail quanta to kill the last-wave straggler
// ---------------------------------------------------------------------------
__global__ __launch_bounds__(256, 1) void lstm_merged(
    const float* __restrict__ games_home, const float* __restrict__ games_away,
    const float* __restrict__ games_vs,
    const float* __restrict__ ph, const float* __restrict__ pa,
    const float* __restrict__ Wih3, const float* __restrict__ Whh3)
{
    extern __shared__ __align__(16) char sm[];
    const u32 sbase = smem_u32(sm);
    const int tid = threadIdx.x, wid = tid >> 5, lane = tid & 31;
    const int g = lane >> 2, tig = lane & 3;

    if (blockIdx.x < 96) {
        // =================== roleA: LSTM1/2, 16 rows ===================
        const int b = blockIdx.x;
        const bool is1 = (b < 64);
        const int row0 = (is1 ? b : (b - 64)) * 16;
        const char* gB = (const char*)(is1 ? g_W1h : g_W2h);

        ((float4*)(sm + SA_BIAS))[tid] = (is1 ? g_b1v4 : g_b2v4)[tid];
        for (int i = tid; i < 2 * ABUFA / 8; i += 256) ((u64*)(sm + SA_A))[i] = 0ull;

        // x loader: 16 rows x 16 threads/row, 1 float4 each
        const int xr = tid >> 4, xq = tid & 15;
        const int gxr = row0 + xr;
        const float* xrowp = is1 ? ((gxr < 512) ? games_home + (size_t)gxr * (T1_ * IN1_)
                                                : games_away + (size_t)(gxr - 512) * (T1_ * IN1_))
                                 : games_vs + (size_t)gxr * (T1_ * IN1_);
        const float4* xsrc = (const float4*)xrowp + xq;
        char* xdst0 = sm + SA_A + xr * APITCH12 + xq * 8;

        const int jq = wid;   // warp covers 32 j for all 4 gates
        const u32 a_addr0 = sbase + SA_A + (u32)((lane & 15) * APITCH12 + (lane >> 4) * 16);
        const u32 b_lane = (u32)((lane & 15) * BPITCH12 + (lane >> 4) * 16);

        char* hs_lo0 = sm + SA_A + g * APITCH12 + (IN1_ + jq * 32 + 2 * tig) * 2;

        float acc[4][4][4];
        float cst[16], hreg[16];
#pragma unroll
        for (int i = 0; i < 16; i++) { cst[i] = 0.0f; hreg[i] = 0.0f; }

        const u32 bufs[3] = { sbase + SA_B0, sbase + SA_B1, sbase + SA_B2 };
        // prefetch tiles 0,1 into bufs 0,1
#pragma unroll
        for (int pt = 0; pt < 2; pt++) {
#pragma unroll
            for (int q = 0; q < 16; q++) {
                int c = tid + 256 * q;
                int row = c >> 7, col = (c & 127) * 16;
                cp16(bufs[pt] + (u32)(row * BPITCH12 + col), gB + (pt * 32 + row) * 2048 + col);
            }
            cp_commit();
        }
        __syncthreads();

        int cur = 0;   // buffer holding current tile
        int nt = 2;    // next tile index to fetch
        for (int t = 0; t < T1_; t++) {
            const int par = (t & 1) * ABUFA;
            // phase 1: x_t + h_{t-1} -> A[par]  (no sync; tile-0 sync orders it)
            float4 xv = __ldg(xsrc + t * 16);
            char* xd = xdst0 + par;
            *(__half2*)(xd)     = __floats2half2_rn(xv.x, xv.y);
            *(__half2*)(xd + 4) = __floats2half2_rn(xv.z, xv.w);
            char* hlo = hs_lo0 + par;
            char* hhi = hlo + 8 * APITCH12;
#pragma unroll
            for (int sub = 0; sub < 4; sub++) {
                *(__half2*)(hlo + sub * 16) = __floats2half2_rn(hreg[sub * 4 + 0], hreg[sub * 4 + 1]);
                *(__half2*)(hhi + sub * 16) = __floats2half2_rn(hreg[sub * 4 + 2], hreg[sub * 4 + 3]);
            }

#pragma unroll
            for (int i = 0; i < 64; i++) ((float*)acc)[i] = 0.0f;

            const u32 a_par = a_addr0 + (u32)par;
            // phase 2: 10 streamed tiles, ONE sync per tile
            for (int kt = 0; kt < 10; kt++) {
                cp_wait<1>();              // current tile landed (per-thread)
                __syncthreads();           // all landed + prev-tile reads done
                // refill the buffer read two tiles ago with tile nt
                {
                    const u32 rbuf = bufs[(cur + 2) % 3];
#pragma unroll
                    for (int q = 0; q < 16; q++) {
                        int c = tid + 256 * q;
                        int row = c >> 7, col = (c & 127) * 16;
                        cp16(rbuf + (u32)(row * BPITCH12 + col), gB + (nt * 32 + row) * 2048 + col);
                    }
                    cp_commit();
                }
                nt = (nt + 1) % 10;
                const u32 buf = bufs[cur];
#pragma unroll
                for (int ks = 0; ks < 2; ks++) {
                    u32 a0, a1, a2, a3;
                    ldsm_x4(a0, a1, a2, a3, a_par + (u32)((kt * 2 + ks) * 32));
                    const u32 bk = buf + b_lane + (u32)(ks * 16 * BPITCH12);
#pragma unroll
                    for (int gi = 0; gi < 4; gi++) {
#pragma unroll
                        for (int sp = 0; sp < 2; sp++) {
                            u32 b0, b1, b2, b3;
                            ldsm_x4t(b0, b1, b2, b3,
                                     bk + (u32)((gi * 256 + jq * 32 + sp * 16) * 2));
                            mma16816(acc[gi][2 * sp],     a0, a1, a2, a3, b0, b1);
                            mma16816(acc[gi][2 * sp + 1], a0, a1, a2, a3, b2, b3);
                        }
                    }
                }
                cur = (cur + 1) % 3;
            }

            // phase 3: cell update (register-local)
            const float4* bias4 = (const float4*)(sm + SA_BIAS);
#pragma unroll
            for (int sub = 0; sub < 4; sub++) {
                const int jb = jq * 32 + sub * 8 + 2 * tig;
#pragma unroll
                for (int cc = 0; cc < 4; cc++) {
                    int j = jb + (cc & 1);
                    float4 b4 = bias4[j];
                    float iv = sga(acc[0][sub][cc] + b4.x);
                    float fv = sga(acc[1][sub][cc] + b4.y);
                    float gv = tapx(acc[2][sub][cc] + b4.z);
                    float ov = sga(acc[3][sub][cc] + b4.w);
                    int ci = sub * 4 + cc;
                    float cn = fv * cst[ci] + iv * gv;
                    cst[ci] = cn;
                    hreg[ci] = ov * tapx(cn);
                }
            }
        }

        // final h -> g_feat
#pragma unroll
        for (int half = 0; half < 2; half++) {
            int gr = row0 + g + half * 8;
            float* fp;
            if (is1) fp = g_feat + (size_t)(gr & 511) * FEATC + ((gr < 512) ? 0 : 256);
            else     fp = g_feat + (size_t)gr * FEATC + 512;
#pragma unroll
            for (int sub = 0; sub < 4; sub++) {
                int j = jq * 32 + sub * 8 + 2 * tig;
                fp[j]     = hreg[sub * 4 + half * 2 + 0];
                fp[j + 1] = hreg[sub * 4 + half * 2 + 1];
            }
        }
    } else if (blockIdx.x < 408) {
        // =================== roleB32: LSTM3, 32 rows ===================
        const int row0 = ((int)blockIdx.x - 96) * 32;
        const int rt = wid >> 2, jq = wid & 3;

        for (int idx = tid; idx < 512 * 160; idx += 256) {
            int n = idx / 160, k = idx - n * 160;
            float v = (k < IN3_) ? Wih3[n * IN3_ + k] : Whh3[n * H3_ + (k - IN3_)];
            *(__half*)(sm + SMB_B + k * BSTRIDE + n * 2) = __float2half_rn(v);
        }
        for (int i = tid; i < 512; i += 256)
            ((float*)(sm + SMB_BIAS))[i] = g_b3[i];
        for (int i = tid; i < 2 * ABUFB / 8; i += 256) ((u64*)(sm + SMB_A))[i] = 0ull;

        const int xr = tid >> 3, xq = tid & 7;
        const int gxr = row0 + xr;
        const bool hmx = (gxr < 6144);
        const int gx2 = hmx ? gxr : gxr - 6144;
        const float4* xsrc = (const float4*)((hmx ? ph : pa) + (size_t)gx2 * (T3_ * IN3_)) + xq;
        char* xdst0 = sm + SMB_A + xr * ASTRIDE + xq * 8;

        const u32 a_addr0 = sbase + SMB_A + (u32)((rt * 16 + (lane & 15)) * ASTRIDE + (lane >> 4) * 16);
        const u32 b_addr = sbase + SMB_B + (u32)((lane & 15) * BSTRIDE + (lane >> 4) * 16);

        char* hs_lo0 = sm + SMB_A + (rt * 16 + g) * ASTRIDE + (IN3_ + jq * 32 + 2 * tig) * 2;

        float acc[4][4][4];
        float cst[16], hreg[16];
#pragma unroll
        for (int i = 0; i < 16; i++) { cst[i] = 0.0f; hreg[i] = 0.0f; }

        __syncthreads();

        for (int t = 0; t < T3_; t++) {
            const int par = (t & 1) * ABUFB;
            float4 xv = __ldg(xsrc + t * 8);
            char* xd = xdst0 + par;
            *(__half2*)(xd)     = __floats2half2_rn(xv.x, xv.y);
            *(__half2*)(xd + 4) = __floats2half2_rn(xv.z, xv.w);
            char* hlo = hs_lo0 + par;
            char* hhi = hlo + 8 * ASTRIDE;
#pragma unroll
            for (int sub = 0; sub < 4; sub++) {
                *(__half2*)(hlo + sub * 16) = __floats2half2_rn(hreg[sub * 4 + 0], hreg[sub * 4 + 1]);
                *(__half2*)(hhi + sub * 16) = __floats2half2_rn(hreg[sub * 4 + 2], hreg[sub * 4 + 3]);
            }
            __syncthreads();

#pragma unroll
            for (int i = 0; i < 64; i++) ((float*)acc)[i] = 0.0f;

            const u32 a_par = a_addr0 + (u32)par;
#pragma unroll
            for (int kt = 0; kt < 10; kt++) {
                u32 a0, a1, a2, a3;
                ldsm_x4(a0, a1, a2, a3, a_par + kt * 32);
#pragma unroll
                for (int gi = 0; gi < 4; gi++) {
#pragma unroll
                    for (int sp = 0; sp < 2; sp++) {
                        u32 b0, b1, b2, b3;
                        ldsm_x4t(b0, b1, b2, b3,
                                 b_addr + (u32)(kt * 16 * BSTRIDE + (gi * 128 + jq * 32 + sp * 16) * 2));
                        mma16816(acc[gi][2 * sp],     a0, a1, a2, a3, b0, b1);
                        mma16816(acc[gi][2 * sp + 1], a0, a1, a2, a3, b2, b3);
                    }
                }
            }
            // no post-MMA sync: next step writes the OTHER A buffer

            const float4* bias4 = (const float4*)(sm + SMB_BIAS);
#pragma unroll
            for (int sub = 0; sub < 4; sub++) {
                const int jb = jq * 32 + sub * 8 + 2 * tig;
#pragma unroll
                for (int cc = 0; cc < 4; cc++) {
                    int j = jb + (cc & 1);
                    float4 b4 = bias4[j];
                    float iv = sga(acc[0][sub][cc] + b4.x);
                    float fv = sga(acc[1][sub][cc] + b4.y);
                    float gv = tapx(acc[2][sub][cc] + b4.z);
                    float ov = sga(acc[3][sub][cc] + b4.w);
                    int ci = sub * 4 + cc;
                    float cn = fv * cst[ci] + iv * gv;
                    cst[ci] = cn;
                    hreg[ci] = ov * tapx(cn);
                }
            }
        }

#pragma unroll
        for (int half = 0; half < 2; half++) {
            int gr = row0 + rt * 16 + g + half * 8;
            bool hm = (gr < 6144);
            int g2 = hm ? gr : gr - 6144;
            int bb = g2 / 12, pp = g2 - 12 * bb;
            float* fp = g_feat + (size_t)bb * FEATC + (hm ? 768 : 2304) + pp * H3_;
#pragma unroll
            for (int sub = 0; sub < 4; sub++) {
                int j = jq * 32 + sub * 8 + 2 * tig;
                fp[j]     = hreg[sub * 4 + half * 2 + 0];
                fp[j + 1] = hreg[sub * 4 + half * 2 + 1];
            }
        }
    } else {
        // =================== roleB16: LSTM3, 16 rows (tail quanta) ===================
        const int row0 = 9984 + ((int)blockIdx.x - 408) * 16;
        const int jq = wid;   // warp covers 16 j for all 4 gates

        for (int idx = tid; idx < 512 * 160; idx += 256) {
            int n = idx / 160, k = idx - n * 160;
            float v = (k < IN3_) ? Wih3[n * IN3_ + k] : Whh3[n * H3_ + (k - IN3_)];
            *(__half*)(sm + SMB_B + k * BSTRIDE + n * 2) = __float2half_rn(v);
        }
        for (int i = tid; i < 512; i += 256)
            ((float*)(sm + SMB_BIAS))[i] = g_b3[i];
        for (int i = tid; i < 2 * ABUFB / 8; i += 256) ((u64*)(sm + SMB_A))[i] = 0ull;

        // x loader: 16 rows x 8 threads/row (tid < 128)
        const int xr = tid >> 3, xq = tid & 7;
        const bool xact = (xr < 16);
        const int gxr = row0 + (xr & 15);
        const bool hmx = (gxr < 6144);
        const int gx2 = hmx ? gxr : gxr - 6144;
        const float4* xsrc = (const float4*)((hmx ? ph : pa) + (size_t)gx2 * (T3_ * IN3_)) + xq;
        char* xdst0 = sm + SMB_A + (xr & 15) * ASTRIDE + xq * 8;

        const u32 a_addr0 = sbase + SMB_A + (u32)((lane & 15) * ASTRIDE + (lane >> 4) * 16);
        const u32 b_addr = sbase + SMB_B + (u32)((lane & 15) * BSTRIDE + (lane >> 4) * 16);

        char* hs_lo0 = sm + SMB_A + g * ASTRIDE + (IN3_ + jq * 16 + 2 * tig) * 2;

        float acc[4][2][4];
        float cst[8], hreg[8];
#pragma unroll
        for (int i = 0; i < 8; i++) { cst[i] = 0.0f; hreg[i] = 0.0f; }

        __syncthreads();

        for (int t = 0; t < T3_; t++) {
            const int par = (t & 1) * ABUFB;
            if (xact) {
                float4 xv = __ldg(xsrc + t * 8);
                char* xd = xdst0 + par;
                *(__half2*)(xd)     = __floats2half2_rn(xv.x, xv.y);
                *(__half2*)(xd + 4) = __floats2half2_rn(xv.z, xv.w);
            }
            char* hlo = hs_lo0 + par;
            char* hhi = hlo + 8 * ASTRIDE;
#pragma unroll
            for (int sub = 0; sub < 2; sub++) {
                *(__half2*)(hlo + sub * 16) = __floats2half2_rn(hreg[sub * 4 + 0], hreg[sub * 4 + 1]);
                *(__half2*)(hhi + sub * 16) = __floats2half2_rn(hreg[sub * 4 + 2], hreg[sub * 4 + 3]);
            }
            __syncthreads();

#pragma unroll
            for (int i = 0; i < 32; i++) ((float*)acc)[i] = 0.0f;

            const u32 a_par = a_addr0 + (u32)par;
#pragma unroll
            for (int kt = 0; kt < 10; kt++) {
                u32 a0, a1, a2, a3;
                ldsm_x4(a0, a1, a2, a3, a_par + kt * 32);
#pragma unroll
                for (int gi = 0; gi < 4; gi++) {
                    u32 b0, b1, b2, b3;
                    ldsm_x4t(b0, b1, b2, b3,
                             b_addr + (u32)(kt * 16 * BSTRIDE + (gi * 128 + jq * 16) * 2));
                    mma16816(acc[gi][0], a0, a1, a2, a3, b0, b1);
                    mma16816(acc[gi][1], a0, a1, a2, a3, b2, b3);
                }
            }
            // no post-MMA sync: next step writes the OTHER A buffer

            const float4* bias4 = (const float4*)(sm + SMB_BIAS);
#pragma unroll
            for (int sub = 0; sub < 2; sub++) {
                const int jb = jq * 16 + sub * 8 + 2 * tig;
#pragma unroll
                for (int cc = 0; cc < 4; cc++) {
                    int j = jb + (cc & 1);
                    float4 b4 = bias4[j];
                    float iv = sga(acc[0][sub][cc] + b4.x);
                    float fv = sga(acc[1][sub][cc] + b4.y);
                    float gv = tapx(acc[2][sub][cc] + b4.z);
                    float ov = sga(acc[3][sub][cc] + b4.w);
                    int ci = sub * 4 + cc;
                    float cn = fv * cst[ci] + iv * gv;
                    cst[ci] = cn;
                    hreg[ci] = ov * tapx(cn);
                }
            }
        }

#pragma unroll
        for (int half = 0; half < 2; half++) {
            int gr = row0 + g + half * 8;
            bool hm = (gr < 6144);
            int g2 = hm ? gr : gr - 6144;
            int bb = g2 / 12, pp = g2 - 12 * bb;
            float* fp = g_feat + (size_t)bb * FEATC + (hm ? 768 : 2304) + pp * H3_;
#pragma unroll
            for (int sub = 0; sub < 2; sub++) {
                int j = jq * 16 + sub * 8 + 2 * tig;
                fp[j]     = hreg[sub * 4 + half * 2 + 0];
                fp[j + 1] = hreg[sub * 4 + half * 2 + 1];
            }
        }
    }
}

// ---------------- FC ----------------
__global__ void fc_kernel(const float* __restrict__ cg, const float* __restrict__ Wfc,
                          const float* __restrict__ bfc, float* __restrict__ out)
{
    const int b = blockIdx.x, tid = threadIdx.x;   // 128 threads
    const float* f = g_feat + b * FEATC;
    float a0 = 0.0f, a1 = 0.0f;
    for (int i = tid; i < FEATC; i += 128) {
        float v = f[i];
        a0 = fmaf(v, Wfc[i], a0);
        a1 = fmaf(v, Wfc[FCIN_ + i], a1);
    }
    if (tid < 32) {
        float v = cg[b * 32 + tid];
        a0 = fmaf(v, Wfc[FEATC + tid], a0);
        a1 = fmaf(v, Wfc[FCIN_ + FEATC + tid], a1);
    }
#pragma unroll
    for (int o = 16; o > 0; o >>= 1) {
        a0 += __shfl_down_sync(0xffffffffu, a0, o);
        a1 += __shfl_down_sync(0xffffffffu, a1, o);
    }
    __shared__ float r0[4], r1[4];
    int w = tid >> 5, l = tid & 31;
    if (l == 0) { r0[w] = a0; r1[w] = a1; }
    __syncthreads();
    if (tid == 0) {
        out[b * 2 + 0] = r0[0] + r0[1] + r0[2] + r0[3] + bfc[0];
        out[b * 2 + 1] = r1[0] + r1[1] + r1[2] + r1[3] + bfc[1];
    }
}

// ---------------- kernel_launch ----------------
extern "C" void kernel_launch(void* const* d_in, const int* in_sizes, int n_in,
                              void* d_out, int out_size)
{
    (void)in_sizes; (void)n_in; (void)out_size;
    const float* current_game = (const float*)d_in[0];
    const float* games_home   = (const float*)d_in[1];
    const float* games_away   = (const float*)d_in[2];
    const float* games_vs     = (const float*)d_in[3];
    const float* players_home = (const float*)d_in[4];
    const float* players_away = (const float*)d_in[5];
    const float* Wih1 = (const float*)d_in[6];
    const float* Whh1 = (const float*)d_in[7];
    const float* bih1 = (const float*)d_in[8];
    const float* bhh1 = (const float*)d_in[9];
    const float* Wih2 = (const float*)d_in[10];
    const float* Whh2 = (const float*)d_in[11];
    const float* bih2 = (const float*)d_in[12];
    const float* bhh2 = (const float*)d_in[13];
    const float* Wih3 = (const float*)d_in[14];
    const float* Whh3 = (const float*)d_in[15];
    const float* bih3 = (const float*)d_in[16];
    const float* bhh3 = (const float*)d_in[17];
    const float* Wfc  = (const float*)d_in[18];
    const float* bfc  = (const float*)d_in[19];

    cudaFuncSetAttribute(lstm_merged, cudaFuncAttributeMaxDynamicSharedMemorySize, SMEM_MERGED);

    prep_kernel<<<1280, 256>>>(Wih1, Whh1, bih1, bhh1,
                               Wih2, Whh2, bih2, bhh2, bih3, bhh3);
    lstm_merged<<<552, 256, SMEM_MERGED>>>(games_home, games_away, games_vs,
                                           players_home, players_away, Wih3, Whh3);
    fc_kernel<<<512, 128>>>(current_game, Wfc, bfc, (float*)d_out);
}

// round 14
// speedup vs baseline: 1.1067x; 1.1067x over previous
#include <cuda_runtime.h>
#include <cuda_fp16.h>
#include <cstdint>

#define B_    512
#define T1_   128
#define IN1_  64
#define H1_   256
#define IN3_  32
#define H3_   128
#define T3_   64
#define FCIN_ 3872
#define FEATC 3840

typedef unsigned long long u64;
typedef unsigned int u32;

// ---------------- device scratch ----------------
__device__ __align__(16) __half g_W1h[320 * 1024];   // [k][n], n=gate*256+j, pitch 2048B
__device__ __align__(16) __half g_W2h[320 * 1024];
__device__ __align__(16) __half g_W3img[160 * 520];  // smem-image of LSTM3 B (pitch 1040B)
__device__ __align__(16) float4 g_b1v4[H1_];         // (bi,bf,bg,bo) per j
__device__ __align__(16) float4 g_b2v4[H1_];
__device__ __align__(16) float  g_b3[H3_ * 4];       // [j][(bi,bf,bg,bo)]
__device__ float g_feat[B_ * FEATC];
__device__ int   g_ctr;                              // steal counter (reset in prep)

#define NCH32 320           // 32-row chunks: rows 0..10239
#define NCH16 128           // 16-row chunks: rows 10240..12287
#define NCHT  (NCH32 + NCH16)

// ---------------- scalar helpers ----------------
__device__ __forceinline__ float tapx(float x) {           // HW tanh (MUFU)
    float y; asm("tanh.approx.f32 %0, %1;" : "=f"(y) : "f"(x)); return y;
}
__device__ __forceinline__ float sga(float x) {            // sigmoid via tanh
    return fmaf(tapx(0.5f * x), 0.5f, 0.5f);
}
__device__ __forceinline__ u32 smem_u32(const void* p) {
    u32 a;
    asm("{ .reg .u64 t; cvta.to.shared.u64 t, %1; cvt.u32.u64 %0, t; }" : "=r"(a) : "l"(p));
    return a;
}

// ---------------- mma.sync / ldmatrix / cp.async ----------------
__device__ __forceinline__ void ldsm_x4(u32& r0, u32& r1, u32& r2, u32& r3, u32 addr) {
    asm volatile("ldmatrix.sync.aligned.m8n8.x4.shared.b16 {%0,%1,%2,%3}, [%4];"
                 : "=r"(r0), "=r"(r1), "=r"(r2), "=r"(r3) : "r"(addr));
}
// x4 trans: {r0,r1} = B-frag of n-tile at n_off, {r2,r3} = n-tile at n_off+8.
__device__ __forceinline__ void ldsm_x4t(u32& r0, u32& r1, u32& r2, u32& r3, u32 addr) {
    asm volatile("ldmatrix.sync.aligned.m8n8.x4.trans.shared.b16 {%0,%1,%2,%3}, [%4];"
                 : "=r"(r0), "=r"(r1), "=r"(r2), "=r"(r3) : "r"(addr));
}
__device__ __forceinline__ void mma16816(float* c, u32 a0, u32 a1, u32 a2, u32 a3,
                                         u32 b0, u32 b1) {
    asm volatile("mma.sync.aligned.m16n8k16.row.col.f32.f16.f16.f32 "
                 "{%0,%1,%2,%3}, {%4,%5,%6,%7}, {%8,%9}, {%0,%1,%2,%3};"
                 : "+f"(c[0]), "+f"(c[1]), "+f"(c[2]), "+f"(c[3])
                 : "r"(a0), "r"(a1), "r"(a2), "r"(a3), "r"(b0), "r"(b1));
}
__device__ __forceinline__ void cp16(u32 saddr, const void* gptr) {
    asm volatile("cp.async.cg.shared.global [%0], [%1], 16;" :: "r"(saddr), "l"(gptr));
}
__device__ __forceinline__ void cp_commit() {
    asm volatile("cp.async.commit_group;" ::: "memory");
}
template<int N> __device__ __forceinline__ void cp_wait() {
    asm volatile("cp.async.wait_group %0;" :: "n"(N) : "memory");
}

// ---------------- roleB (lstm3) smem layout: double-buffered A ----------------
#define ASTRIDE 336
#define BSTRIDE 1040
#define ABUFB   10752            // 32 rows x 336 (16-row chunks use half, same spacing)
#define SMB_A    0               // A0 at 0, A1 at 10752
#define SMB_BIAS 21504           // 2048 (float4[128])
#define SMB_CTR  23552           // 16B: stolen chunk id
#define SMB_B    23568           // + 160*1040 = 189968

// ---------------- roleA (lstm12, 16 rows) smem layout: 2xA + 3xB ----------------
#define APITCH12  656            // 16 rows x 656B = 10496
#define ABUFA     10496
#define BPITCH12  2064
#define TILE12    66048          // 32*2064
#define SA_A      0              // A0 at 0, A1 at 10496
#define SA_BIAS   20992          // float4[256] = 4096
#define SA_B0     25088
#define SA_B1     (SA_B0 + TILE12)
#define SA_B2     (SA_B1 + TILE12)
#define SMEM_MERGED (SA_B2 + TILE12)   // 223232 <= 227KB cap

// ---------------- weight prep ----------------
__global__ void prep_kernel(
    const float* __restrict__ Wih1, const float* __restrict__ Whh1,
    const float* __restrict__ bih1, const float* __restrict__ bhh1,
    const float* __restrict__ Wih2, const float* __restrict__ Whh2,
    const float* __restrict__ bih2, const float* __restrict__ bhh2,
    const float* __restrict__ Wih3, const float* __restrict__ Whh3,
    const float* __restrict__ bih3, const float* __restrict__ bhh3)
{
    int idx = blockIdx.x * blockDim.x + threadIdx.x;
    if (idx == 0) g_ctr = 0;                 // reset steal queue every launch/replay
    if (idx < 320 * 1024) {
        int k = idx >> 10, n = idx & 1023;
        int tau = n >> 8, j = n & 255;
        int g = tau * H1_ + j;
        float v1 = (k < IN1_) ? Wih1[g * IN1_ + k] : Whh1[g * H1_ + (k - IN1_)];
        float v2 = (k < IN1_) ? Wih2[g * IN1_ + k] : Whh2[g * H1_ + (k - IN1_)];
        g_W1h[idx] = __float2half_rn(v1);
        g_W2h[idx] = __float2half_rn(v2);
    }
    if (idx < 160 * 520) {
        int k = idx / 520, n = idx - k * 520;
        float v = 0.0f;
        if (n < 512) v = (k < IN3_) ? Wih3[n * IN3_ + k] : Whh3[n * H3_ + (k - IN3_)];
        g_W3img[idx] = __float2half_rn(v);
    }
    if (idx < H1_) {
        int j = idx;
        g_b1v4[j] = make_float4(bih1[j] + bhh1[j],
                                bih1[H1_ + j] + bhh1[H1_ + j],
                                bih1[2 * H1_ + j] + bhh1[2 * H1_ + j],
                                bih1[3 * H1_ + j] + bhh1[3 * H1_ + j]);
        g_b2v4[j] = make_float4(bih2[j] + bhh2[j],
                                bih2[H1_ + j] + bhh2[H1_ + j],
                                bih2[2 * H1_ + j] + bhh2[2 * H1_ + j],
                                bih2[3 * H1_ + j] + bhh2[3 * H1_ + j]);
    }
    if (idx < H3_ * 4) {
        int tau = idx & 3, j = idx >> 2;
        g_b3[j * 4 + tau] = bih3[tau * H3_ + j] + bhh3[tau * H3_ + j];
    }
}

// ---------------------------------------------------------------------------
// LSTM3 chunk processors (B + bias already resident in smem)
// ---------------------------------------------------------------------------
__device__ __forceinline__ void run_b32(int row0, char* sm, u32 sbase,
                                        int tid, int wid, int lane, int g, int tig,
                                        const float* __restrict__ ph,
                                        const float* __restrict__ pa)
{
    const int rt = wid >> 2, jq = wid & 3;

    for (int i = tid; i < 2 * ABUFB / 8; i += 256) ((u64*)(sm + SMB_A))[i] = 0ull;

    const int xr = tid >> 3, xq = tid & 7;
    const int gxr = row0 + xr;
    const bool hmx = (gxr < 6144);
    const int gx2 = hmx ? gxr : gxr - 6144;
    const float4* xsrc = (const float4*)((hmx ? ph : pa) + (size_t)gx2 * (T3_ * IN3_)) + xq;
    char* xdst0 = sm + SMB_A + xr * ASTRIDE + xq * 8;

    const u32 a_addr0 = sbase + SMB_A + (u32)((rt * 16 + (lane & 15)) * ASTRIDE + (lane >> 4) * 16);
    const u32 b_addr = sbase + SMB_B + (u32)((lane & 15) * BSTRIDE + (lane >> 4) * 16);

    char* hs_lo0 = sm + SMB_A + (rt * 16 + g) * ASTRIDE + (IN3_ + jq * 32 + 2 * tig) * 2;

    float acc[4][4][4];
    float cst[16], hreg[16];
#pragma unroll
    for (int i = 0; i < 16; i++) { cst[i] = 0.0f; hreg[i] = 0.0f; }

    __syncthreads();

    for (int t = 0; t < T3_; t++) {
        const int par = (t & 1) * ABUFB;
        float4 xv = __ldg(xsrc + t * 8);
        char* xd = xdst0 + par;
        *(__half2*)(xd)     = __floats2half2_rn(xv.x, xv.y);
        *(__half2*)(xd + 4) = __floats2half2_rn(xv.z, xv.w);
        char* hlo = hs_lo0 + par;
        char* hhi = hlo + 8 * ASTRIDE;
#pragma unroll
        for (int sub = 0; sub < 4; sub++) {
            *(__half2*)(hlo + sub * 16) = __floats2half2_rn(hreg[sub * 4 + 0], hreg[sub * 4 + 1]);
            *(__half2*)(hhi + sub * 16) = __floats2half2_rn(hreg[sub * 4 + 2], hreg[sub * 4 + 3]);
        }
        __syncthreads();

#pragma unroll
        for (int i = 0; i < 64; i++) ((float*)acc)[i] = 0.0f;

        const u32 a_par = a_addr0 + (u32)par;
#pragma unroll
        for (int kt = 0; kt < 10; kt++) {
            u32 a0, a1, a2, a3;
            ldsm_x4(a0, a1, a2, a3, a_par + kt * 32);
#pragma unroll
            for (int gi = 0; gi < 4; gi++) {
#pragma unroll
                for (int sp = 0; sp < 2; sp++) {
                    u32 b0, b1, b2, b3;
                    ldsm_x4t(b0, b1, b2, b3,
                             b_addr + (u32)(kt * 16 * BSTRIDE + (gi * 128 + jq * 32 + sp * 16) * 2));
                    mma16816(acc[gi][2 * sp],     a0, a1, a2, a3, b0, b1);
                    mma16816(acc[gi][2 * sp + 1], a0, a1, a2, a3, b2, b3);
                }
            }
        }
        // no post-MMA sync: next step writes the OTHER A buffer

        const float4* bias4 = (const float4*)(sm + SMB_BIAS);
#pragma unroll
        for (int sub = 0; sub < 4; sub++) {
            const int jb = jq * 32 + sub * 8 + 2 * tig;
#pragma unroll
            for (int cc = 0; cc < 4; cc++) {
                int j = jb + (cc & 1);
                float4 b4 = bias4[j];
                float iv = sga(acc[0][sub][cc] + b4.x);
                float fv = sga(acc[1][sub][cc] + b4.y);
                float gv = tapx(acc[2][sub][cc] + b4.z);
                float ov = sga(acc[3][sub][cc] + b4.w);
                int ci = sub * 4 + cc;
                float cn = fv * cst[ci] + iv * gv;
                cst[ci] = cn;
                hreg[ci] = ov * tapx(cn);
            }
        }
    }

#pragma unroll
    for (int half = 0; half < 2; half++) {
        int gr = row0 + rt * 16 + g + half * 8;
        bool hm = (gr < 6144);
        int g2 = hm ? gr : gr - 6144;
        int bb = g2 / 12, pp = g2 - 12 * bb;
        float* fp = g_feat + (size_t)bb * FEATC + (hm ? 768 : 2304) + pp * H3_;
#pragma unroll
        for (int sub = 0; sub < 4; sub++) {
            int j = jq * 32 + sub * 8 + 2 * tig;
            fp[j]     = hreg[sub * 4 + half * 2 + 0];
            fp[j + 1] = hreg[sub * 4 + half * 2 + 1];
        }
    }
}

__device__ __forceinline__ void run_b16(int row0, char* sm, u32 sbase,
                                        int tid, int wid, int lane, int g, int tig,
                                        const float* __restrict__ ph,
                                        const float* __restrict__ pa)
{
    const int jq = wid;   // warp covers 16 j for all 4 gates

    for (int i = tid; i < 2 * ABUFB / 8; i += 256) ((u64*)(sm + SMB_A))[i] = 0ull;

    const int xr = tid >> 3, xq = tid & 7;
    const bool xact = (xr < 16);
    const int gxr = row0 + (xr & 15);
    const bool hmx = (gxr < 6144);
    const int gx2 = hmx ? gxr : gxr - 6144;
    const float4* xsrc = (const float4*)((hmx ? ph : pa) + (size_t)gx2 * (T3_ * IN3_)) + xq;
    char* xdst0 = sm + SMB_A + (xr & 15) * ASTRIDE + xq * 8;

    const u32 a_addr0 = sbase + SMB_A + (u32)((lane & 15) * ASTRIDE + (lane >> 4) * 16);
    const u32 b_addr = sbase + SMB_B + (u32)((lane & 15) * BSTRIDE + (lane >> 4) * 16);

    char* hs_lo0 = sm + SMB_A + g * ASTRIDE + (IN3_ + jq * 16 + 2 * tig) * 2;

    float acc[4][2][4];
    float cst[8], hreg[8];
#pragma unroll
    for (int i = 0; i < 8; i++) { cst[i] = 0.0f; hreg[i] = 0.0f; }

    __syncthreads();

    for (int t = 0; t < T3_; t++) {
        const int par = (t & 1) * ABUFB;
        if (xact) {
            float4 xv = __ldg(xsrc + t * 8);
            char* xd = xdst0 + par;
            *(__half2*)(xd)     = __floats2half2_rn(xv.x, xv.y);
            *(__half2*)(xd + 4) = __floats2half2_rn(xv.z, xv.w);
        }
        char* hlo = hs_lo0 + par;
        char* hhi = hlo + 8 * ASTRIDE;
#pragma unroll
        for (int sub = 0; sub < 2; sub++) {
            *(__half2*)(hlo + sub * 16) = __floats2half2_rn(hreg[sub * 4 + 0], hreg[sub * 4 + 1]);
            *(__half2*)(hhi + sub * 16) = __floats2half2_rn(hreg[sub * 4 + 2], hreg[sub * 4 + 3]);
        }
        __syncthreads();

#pragma unroll
        for (int i = 0; i < 32; i++) ((float*)acc)[i] = 0.0f;

        const u32 a_par = a_addr0 + (u32)par;
#pragma unroll
        for (int kt = 0; kt < 10; kt++) {
            u32 a0, a1, a2, a3;
            ldsm_x4(a0, a1, a2, a3, a_par + kt * 32);
#pragma unroll
            for (int gi = 0; gi < 4; gi++) {
                u32 b0, b1, b2, b3;
                ldsm_x4t(b0, b1, b2, b3,
                         b_addr + (u32)(kt * 16 * BSTRIDE + (gi * 128 + jq * 16) * 2));
                mma16816(acc[gi][0], a0, a1, a2, a3, b0, b1);
                mma16816(acc[gi][1], a0, a1, a2, a3, b2, b3);
            }
        }

        const float4* bias4 = (const float4*)(sm + SMB_BIAS);
#pragma unroll
        for (int sub = 0; sub < 2; sub++) {
            const int jb = jq * 16 + sub * 8 + 2 * tig;
#pragma unroll
            for (int cc = 0; cc < 4; cc++) {
                int j = jb + (cc & 1);
                float4 b4 = bias4[j];
                float iv = sga(acc[0][sub][cc] + b4.x);
                float fv = sga(acc[1][sub][cc] + b4.y);
                float gv = tapx(acc[2][sub][cc] + b4.z);
                float ov = sga(acc[3][sub][cc] + b4.w);
                int ci = sub * 4 + cc;
                float cn = fv * cst[ci] + iv * gv;
                cst[ci] = cn;
                hreg[ci] = ov * tapx(cn);
            }
        }
    }

#pragma unroll
    for (int half = 0; half < 2; half++) {
        int gr = row0 + g + half * 8;
        bool hm = (gr < 6144);
        int g2 = hm ? gr : gr - 6144;
        int bb = g2 / 12, pp = g2 - 12 * bb;
        float* fp = g_feat + (size_t)bb * FEATC + (hm ? 768 : 2304) + pp * H3_;
#pragma unroll
        for (int sub = 0; sub < 2; sub++) {
            int j = jq * 16 + sub * 8 + 2 * tig;
            fp[j]     = hreg[sub * 4 + half * 2 + 0];
            fp[j + 1] = hreg[sub * 4 + half * 2 + 1];
        }
    }
}

// ---------------------------------------------------------------------------
// Merged persistent kernel: 152 blocks x 256 threads (1 block/SM).
//   blocks 0..95  : roleA (LSTM1/2, R12-proven) then morph into LSTM3 stealer
//   blocks 96..151: LSTM3 stealers from t=0
// Stealers fill B once (cp.async from pre-transposed image), then drain an
// atomic queue of 320 32-row + 128 16-row LSTM3 chunks.
// ---------------------------------------------------------------------------
__global__ __launch_bounds__(256, 1) void lstm_merged(
    const float* __restrict__ games_home, const float* __restrict__ games_away,
    const float* __restrict__ games_vs,
    const float* __restrict__ ph, const float* __restrict__ pa)
{
    extern __shared__ __align__(16) char sm[];
    const u32 sbase = smem_u32(sm);
    const int tid = threadIdx.x, wid = tid >> 5, lane = tid & 31;
    const int g = lane >> 2, tig = lane & 3;

    if (blockIdx.x < 96) {
        // =================== roleA: LSTM1/2, 16 rows (R12-proven) ===================
        const int b = blockIdx.x;
        const bool is1 = (b < 64);
        const int row0 = (is1 ? b : (b - 64)) * 16;
        const char* gB = (const char*)(is1 ? g_W1h : g_W2h);

        ((float4*)(sm + SA_BIAS))[tid] = (is1 ? g_b1v4 : g_b2v4)[tid];
        for (int i = tid; i < 2 * ABUFA / 8; i += 256) ((u64*)(sm + SA_A))[i] = 0ull;

        const int xr = tid >> 4, xq = tid & 15;
        const int gxr = row0 + xr;
        const float* xrowp = is1 ? ((gxr < 512) ? games_home + (size_t)gxr * (T1_ * IN1_)
                                                : games_away + (size_t)(gxr - 512) * (T1_ * IN1_))
                                 : games_vs + (size_t)gxr * (T1_ * IN1_);
        const float4* xsrc = (const float4*)xrowp + xq;
        char* xdst0 = sm + SA_A + xr * APITCH12 + xq * 8;

        const int jq = wid;
        const u32 a_addr0 = sbase + SA_A + (u32)((lane & 15) * APITCH12 + (lane >> 4) * 16);
        const u32 b_lane = (u32)((lane & 15) * BPITCH12 + (lane >> 4) * 16);

        char* hs_lo0 = sm + SA_A + g * APITCH12 + (IN1_ + jq * 32 + 2 * tig) * 2;

        float acc[4][4][4];
        float cst[16], hreg[16];
#pragma unroll
        for (int i = 0; i < 16; i++) { cst[i] = 0.0f; hreg[i] = 0.0f; }

        const u32 bufs[3] = { sbase + SA_B0, sbase + SA_B1, sbase + SA_B2 };
#pragma unroll
        for (int pt = 0; pt < 2; pt++) {
#pragma unroll
            for (int q = 0; q < 16; q++) {
                int c = tid + 256 * q;
                int row = c >> 7, col = (c & 127) * 16;
                cp16(bufs[pt] + (u32)(row * BPITCH12 + col), gB + (pt * 32 + row) * 2048 + col);
            }
            cp_commit();
        }
        __syncthreads();

        int cur = 0;
        int nt = 2;
        for (int t = 0; t < T1_; t++) {
            const int par = (t & 1) * ABUFA;
            float4 xv = __ldg(xsrc + t * 16);
            char* xd = xdst0 + par;
            *(__half2*)(xd)     = __floats2half2_rn(xv.x, xv.y);
            *(__half2*)(xd + 4) = __floats2half2_rn(xv.z, xv.w);
            char* hlo = hs_lo0 + par;
            char* hhi = hlo + 8 * APITCH12;
#pragma unroll
            for (int sub = 0; sub < 4; sub++) {
                *(__half2*)(hlo + sub * 16) = __floats2half2_rn(hreg[sub * 4 + 0], hreg[sub * 4 + 1]);
                *(__half2*)(hhi + sub * 16) = __floats2half2_rn(hreg[sub * 4 + 2], hreg[sub * 4 + 3]);
            }

#pragma unroll
            for (int i = 0; i < 64; i++) ((float*)acc)[i] = 0.0f;

            const u32 a_par = a_addr0 + (u32)par;
            for (int kt = 0; kt < 10; kt++) {
                cp_wait<1>();
                __syncthreads();
                {
                    const u32 rbuf = bufs[(cur + 2) % 3];
#pragma unroll
                    for (int q = 0; q < 16; q++) {
                        int c = tid + 256 * q;
                        int row = c >> 7, col = (c & 127) * 16;
                        cp16(rbuf + (u32)(row * BPITCH12 + col), gB + (nt * 32 + row) * 2048 + col);
                    }
                    cp_commit();
                }
                nt = (nt + 1) % 10;
                const u32 buf = bufs[cur];
#pragma unroll
                for (int ks = 0; ks < 2; ks++) {
                    u32 a0, a1, a2, a3;
                    ldsm_x4(a0, a1, a2, a3, a_par + (u32)((kt * 2 + ks) * 32));
                    const u32 bk = buf + b_lane + (u32)(ks * 16 * BPITCH12);
#pragma unroll
                    for (int gi = 0; gi < 4; gi++) {
#pragma unroll
                        for (int sp = 0; sp < 2; sp++) {
                            u32 b0, b1, b2, b3;
                            ldsm_x4t(b0, b1, b2, b3,
                                     bk + (u32)((gi * 256 + jq * 32 + sp * 16) * 2));
                            mma16816(acc[gi][2 * sp],     a0, a1, a2, a3, b0, b1);
                            mma16816(acc[gi][2 * sp + 1], a0, a1, a2, a3, b2, b3);
                        }
                    }
                }
                cur = (cur + 1) % 3;
            }

            const float4* bias4 = (const float4*)(sm + SA_BIAS);
#pragma unroll
            for (int sub = 0; sub < 4; sub++) {
                const int jb = jq * 32 + sub * 8 + 2 * tig;
#pragma unroll
                for (int cc = 0; cc < 4; cc++) {
                    int j = jb + (cc & 1);
                    float4 b4 = bias4[j];
                    float iv = sga(acc[0][sub][cc] + b4.x);
                    float fv = sga(acc[1][sub][cc] + b4.y);
                    float gv = tapx(acc[2][sub][cc] + b4.z);
                    float ov = sga(acc[3][sub][cc] + b4.w);
                    int ci = sub * 4 + cc;
                    float cn = fv * cst[ci] + iv * gv;
                    cst[ci] = cn;
                    hreg[ci] = ov * tapx(cn);
                }
            }
        }

#pragma unroll
        for (int half = 0; half < 2; half++) {
            int gr = row0 + g + half * 8;
            float* fp;
            if (is1) fp = g_feat + (size_t)(gr & 511) * FEATC + ((gr < 512) ? 0 : 256);
            else     fp = g_feat + (size_t)gr * FEATC + 512;
#pragma unroll
            for (int sub = 0; sub < 4; sub++) {
                int j = jq * 32 + sub * 8 + 2 * tig;
                fp[j]     = hreg[sub * 4 + half * 2 + 0];
                fp[j + 1] = hreg[sub * 4 + half * 2 + 1];
            }
        }

        cp_wait<0>();         // drain outstanding roleA B-prefetches
        __syncthreads();      // smem handoff to stealer layout
    }

    // =================== LSTM3 stealer (all blocks) ===================
    // Fill B once from the pre-transposed image (flat copy, identical layout).
    for (int i = tid; i < 10400; i += 256)
        cp16(sbase + SMB_B + (u32)(i * 16), (const char*)g_W3img + i * 16);
    cp_commit();
    cp_wait<0>();
    for (int i = tid; i < 512; i += 256)
        ((float*)(sm + SMB_BIAS))[i] = g_b3[i];
    __syncthreads();

    while (true) {
        if (tid == 0) *(volatile int*)(sm + SMB_CTR) = atomicAdd(&g_ctr, 1);
        __syncthreads();
        int c = *(volatile int*)(sm + SMB_CTR);
        if (c >= NCHT) break;
        if (c < NCH32) run_b32(c * 32, sm, sbase, tid, wid, lane, g, tig, ph, pa);
        else           run_b16(NCH32 * 32 + (c - NCH32) * 16, sm, sbase, tid, wid, lane, g, tig, ph, pa);
    }
}

// ---------------- FC ----------------
__global__ void fc_kernel(const float* __restrict__ cg, const float* __restrict__ Wfc,
                          const float* __restrict__ bfc, float* __restrict__ out)
{
    const int b = blockIdx.x, tid = threadIdx.x;   // 128 threads
    const float* f = g_feat + b * FEATC;
    float a0 = 0.0f, a1 = 0.0f;
    for (int i = tid; i < FEATC; i += 128) {
        float v = f[i];
        a0 = fmaf(v, Wfc[i], a0);
        a1 = fmaf(v, Wfc[FCIN_ + i], a1);
    }
    if (tid < 32) {
        float v = cg[b * 32 + tid];
        a0 = fmaf(v, Wfc[FEATC + tid], a0);
        a1 = fmaf(v, Wfc[FCIN_ + FEATC + tid], a1);
    }
#pragma unroll
    for (int o = 16; o > 0; o >>= 1) {
        a0 += __shfl_down_sync(0xffffffffu, a0, o);
        a1 += __shfl_down_sync(0xffffffffu, a1, o);
    }
    __shared__ float r0[4], r1[4];
    int w = tid >> 5, l = tid & 31;
    if (l == 0) { r0[w] = a0; r1[w] = a1; }
    __syncthreads();
    if (tid == 0) {
        out[b * 2 + 0] = r0[0] + r0[1] + r0[2] + r0[3] + bfc[0];
        out[b * 2 + 1] = r1[0] + r1[1] + r1[2] + r1[3] + bfc[1];
    }
}

// ---------------- kernel_launch ----------------
extern "C" void kernel_launch(void* const* d_in, const int* in_sizes, int n_in,
                              void* d_out, int out_size)
{
    (void)in_sizes; (void)n_in; (void)out_size;
    const float* current_game = (const float*)d_in[0];
    const float* games_home   = (const float*)d_in[1];
    const float* games_away   = (const float*)d_in[2];
    const float* games_vs     = (const float*)d_in[3];
    const float* players_home = (const float*)d_in[4];
    const float* players_away = (const float*)d_in[5];
    const float* Wih1 = (const float*)d_in[6];
    const float* Whh1 = (const float*)d_in[7];
    const float* bih1 = (const float*)d_in[8];
    const float* bhh1 = (const float*)d_in[9];
    const float* Wih2 = (const float*)d_in[10];
    const float* Whh2 = (const float*)d_in[11];
    const float* bih2 = (const float*)d_in[12];
    const float* bhh2 = (const float*)d_in[13];
    const float* Wih3 = (const float*)d_in[14];
    const float* Whh3 = (const float*)d_in[15];
    const float* bih3 = (const float*)d_in[16];
    const float* bhh3 = (const float*)d_in[17];
    const float* Wfc  = (const float*)d_in[18];
    const float* bfc  = (const float*)d_in[19];

    cudaFuncSetAttribute(lstm_merged, cudaFuncAttributeMaxDynamicSharedMemorySize, SMEM_MERGED);

    prep_kernel<<<1280, 256>>>(Wih1, Whh1, bih1, bhh1,
                               Wih2, Whh2, bih2, bhh2,
                               Wih3, Whh3, bih3, bhh3);
    lstm_merged<<<152, 256, SMEM_MERGED>>>(games_home, games_away, games_vs,
                                           players_home, players_away);
    fc_kernel<<<512, 128>>>(current_game, Wfc, bfc, (float*)d_out);
}